// round 7
// baseline (speedup 1.0000x reference)
#include <cuda_runtime.h>
#include <cuda_bf16.h>

// TensorProductScatter: per-edge e3nn tensor product + scatter-add.
// R3 design: 4 edges per warp, ALL loads for the 4 edges issued up front
// (~45 outstanding LDG/warp) to fix the latency-bound profile (issue 33%,
// no pipe >73%). Compute/stage/flush runs sequentially afterwards, reusing
// one 352-float smem row per warp. Flush: red.global.add.v4.f32.

#define MULC 32
#define ROWF 352            // 32 + 96 + 96 + 32 + 96
#define WARPS_PER_BLOCK 8
#define EPW 4               // edges per warp

__device__ __forceinline__ void red_add_v4(float* p, float4 v) {
    asm volatile("red.global.add.v4.f32 [%0], {%1, %2, %3, %4};"
                 :: "l"(p), "f"(v.x), "f"(v.y), "f"(v.z), "f"(v.w)
                 : "memory");
}

__global__ void tps_zero_kernel(float4* __restrict__ out, int n4) {
    int i = blockIdx.x * blockDim.x + threadIdx.x;
    if (i < n4) out[i] = make_float4(0.f, 0.f, 0.f, 0.f);
}

__global__ __launch_bounds__(WARPS_PER_BLOCK * 32)
void tps_scatter_kernel(const float* __restrict__ x,
                        const float* __restrict__ edge_attr,
                        const float* __restrict__ edge_weight,
                        const int*   __restrict__ edge_dst,
                        const int*   __restrict__ edge_src,
                        float*       __restrict__ out,
                        int E) {
    __shared__ __align__(16) float sm_o[WARPS_PER_BLOCK][ROWF];

    const int wb   = threadIdx.x >> 5;
    const int lane = threadIdx.x & 31;
    const long long ebase =
        ((long long)blockIdx.x * WARPS_PER_BLOCK + wb) * EPW;
    if (ebase >= E) return;

    // ---------------- Phase 1: issue ALL loads for EPW edges ----------------
    int   s[EPW], d[EPW];
    float a0[EPW], a1x[EPW], a1y[EPW], a1z[EPW];
    float xs0[EPW], x1a[EPW], x1b[EPW], x1c[EPW];
    float w0[EPW], w1[EPW], w2[EPW], w3[EPW], w4[EPW];

    #pragma unroll
    for (int k = 0; k < EPW; k++) {
        long long e = ebase + k; if (e >= E) e = E - 1;   // clamp (flush guarded later)
        s[k] = edge_src[e];
        d[k] = edge_dst[e];
        const float4 a = __ldg(reinterpret_cast<const float4*>(edge_attr) + e);
        a0[k] = a.x; a1x[k] = a.y; a1y[k] = a.z; a1z[k] = a.w;
    }

    #pragma unroll
    for (int k = 0; k < EPW; k++) {
        const float* xrow = x + (long long)s[k] * (4 * MULC);
        xs0[k] = __ldg(xrow + lane);
        x1a[k] = __ldg(xrow + MULC + 3 * lane + 0);
        x1b[k] = __ldg(xrow + MULC + 3 * lane + 1);
        x1c[k] = __ldg(xrow + MULC + 3 * lane + 2);
    }

    #pragma unroll
    for (int k = 0; k < EPW; k++) {
        long long e = ebase + k; if (e >= E) e = E - 1;
        const float* wrow = edge_weight + e * (5 * MULC);
        w0[k] = __ldcs(wrow + 0 * MULC + lane);
        w1[k] = __ldcs(wrow + 1 * MULC + lane);
        w2[k] = __ldcs(wrow + 2 * MULC + lane);
        w3[k] = __ldcs(wrow + 3 * MULC + lane);
        w4[k] = __ldcs(wrow + 4 * MULC + lane);
    }

    // ---------------- Phase 2: compute + stage + flush per edge -------------
    const float INV_SQRT3 = 0.5773502691896258f;
    const float INV_SQRT2 = 0.7071067811865476f;
    float* r = sm_o[wb];

    #pragma unroll
    for (int k = 0; k < EPW; k++) {
        if (ebase + k >= E) break;                 // warp-uniform guard

        const float o0  = w0[k] * xs0[k] * a0[k];
        const float w1x = w1[k] * xs0[k];
        const float o1x = w1x * a1x[k], o1y = w1x * a1y[k], o1z = w1x * a1z[k];
        const float w2a = w2[k] * a0[k];
        const float o2x = w2a * x1a[k], o2y = w2a * x1b[k], o2z = w2a * x1c[k];
        const float dot = x1a[k] * a1x[k] + x1b[k] * a1y[k] + x1c[k] * a1z[k];
        const float o3  = w3[k] * dot * INV_SQRT3;
        const float cx  = x1b[k] * a1z[k] - x1c[k] * a1y[k];
        const float cy  = x1c[k] * a1x[k] - x1a[k] * a1z[k];
        const float cz  = x1a[k] * a1y[k] - x1b[k] * a1x[k];
        const float w4s = w4[k] * INV_SQRT2;
        const float o4x = w4s * cx, o4y = w4s * cy, o4z = w4s * cz;

        // Stage (stride-3: gcd(3,32)=1 -> conflict-free)
        r[lane]                = o0;
        r[MULC + 3 * lane + 0] = o1x;
        r[MULC + 3 * lane + 1] = o1y;
        r[MULC + 3 * lane + 2] = o1z;
        r[128  + 3 * lane + 0] = o2x;
        r[128  + 3 * lane + 1] = o2y;
        r[128  + 3 * lane + 2] = o2z;
        r[224  + lane]         = o3;
        r[256  + 3 * lane + 0] = o4x;
        r[256  + 3 * lane + 1] = o4y;
        r[256  + 3 * lane + 2] = o4z;
        __syncwarp();

        // Flush: 88 float4 chunks, coalesced 16B vector reductions
        const float4* rv = reinterpret_cast<const float4*>(r);
        float* orow = out + (long long)d[k] * ROWF;
        #pragma unroll
        for (int c = lane; c < ROWF / 4; c += 32) {
            red_add_v4(orow + 4 * c, rv[c]);
        }
        __syncwarp();   // smem row reused next k: flush LDS must complete first
    }
}

extern "C" void kernel_launch(void* const* d_in, const int* in_sizes, int n_in,
                              void* d_out, int out_size) {
    const float* x           = (const float*)d_in[0];
    const float* edge_attr   = (const float*)d_in[1];
    const float* edge_weight = (const float*)d_in[2];
    const int*   edge_dst    = (const int*)d_in[3];
    const int*   edge_src    = (const int*)d_in[4];
    float* out = (float*)d_out;

    const int E = in_sizes[3];

    int n4 = out_size / 4;
    tps_zero_kernel<<<(n4 + 255) / 256, 256>>>((float4*)out, n4);

    const int edges_per_block = WARPS_PER_BLOCK * EPW;
    int blocks = (E + edges_per_block - 1) / edges_per_block;
    tps_scatter_kernel<<<blocks, WARPS_PER_BLOCK * 32>>>(
        x, edge_attr, edge_weight, edge_dst, edge_src, out, E);
}

// round 8
// speedup vs baseline: 1.1050x; 1.1050x over previous
#include <cuda_runtime.h>
#include <cuda_bf16.h>
#include <cstdint>

// TensorProductScatter: per-edge e3nn tensor product + scatter-add.
// R1 design (warp-per-edge, smem-staged row) with the flush offloaded to the
// TMA engine: cp.reduce.async.bulk.global.shared::cta.add.f32 reads the staged
// 1408 B row straight from SMEM and reduces into out[dst] — eliminating the
// LDS readback (12 wf) and REDG pass-through (11 wf) that made the kernel
// L1tex-throughput-bound (~52 wavefronts/edge -> ~29).

#define MULC 32
#define ROWF 352            // 32 + 96 + 96 + 32 + 96
#define WARPS_PER_BLOCK 8

__device__ __forceinline__ uint32_t smem_u32(const void* p) {
    uint32_t a;
    asm("{ .reg .u64 t; cvta.to.shared.u64 t, %1; cvt.u32.u64 %0, t; }"
        : "=r"(a) : "l"(p));
    return a;
}

__global__ void tps_zero_kernel(float4* __restrict__ out, int n4) {
    int i = blockIdx.x * blockDim.x + threadIdx.x;
    if (i < n4) out[i] = make_float4(0.f, 0.f, 0.f, 0.f);
}

__global__ __launch_bounds__(WARPS_PER_BLOCK * 32)
void tps_scatter_kernel(const float* __restrict__ x,
                        const float* __restrict__ edge_attr,
                        const float* __restrict__ edge_weight,
                        const int*   __restrict__ edge_dst,
                        const int*   __restrict__ edge_src,
                        float*       __restrict__ out,
                        int E) {
    __shared__ __align__(16) float sm_o[WARPS_PER_BLOCK][ROWF];

    const int wb   = threadIdx.x >> 5;
    const int lane = threadIdx.x & 31;
    const long long e = (long long)blockIdx.x * WARPS_PER_BLOCK + wb;
    if (e >= E) return;

    // Uniform (warp-broadcast) loads
    const int s = edge_src[e];
    const int d = edge_dst[e];
    const float4 a = __ldg(reinterpret_cast<const float4*>(edge_attr) + e);
    const float a0 = a.x, a1x = a.y, a1y = a.z, a1z = a.w;

    // x gather: L2-resident table (25.6 MB)
    const float* xrow = x + (long long)s * (4 * MULC);
    const float xs0 = __ldg(xrow + lane);
    const float x1a = __ldg(xrow + MULC + 3 * lane + 0);
    const float x1b = __ldg(xrow + MULC + 3 * lane + 1);
    const float x1c = __ldg(xrow + MULC + 3 * lane + 2);

    // Streaming weights (read-once: evict-first)
    const float* wrow = edge_weight + e * (5 * MULC);
    const float w0 = __ldcs(wrow + 0 * MULC + lane);
    const float w1 = __ldcs(wrow + 1 * MULC + lane);
    const float w2 = __ldcs(wrow + 2 * MULC + lane);
    const float w3 = __ldcs(wrow + 3 * MULC + lane);
    const float w4 = __ldcs(wrow + 4 * MULC + lane);

    const float INV_SQRT3 = 0.5773502691896258f;
    const float INV_SQRT2 = 0.7071067811865476f;

    const float o0  = w0 * xs0 * a0;
    const float w1x = w1 * xs0;
    const float o1x = w1x * a1x, o1y = w1x * a1y, o1z = w1x * a1z;
    const float w2a = w2 * a0;
    const float o2x = w2a * x1a, o2y = w2a * x1b, o2z = w2a * x1c;
    const float dot = x1a * a1x + x1b * a1y + x1c * a1z;
    const float o3  = w3 * dot * INV_SQRT3;
    const float cx  = x1b * a1z - x1c * a1y;
    const float cy  = x1c * a1x - x1a * a1z;
    const float cz  = x1a * a1y - x1b * a1x;
    const float w4s = w4 * INV_SQRT2;
    const float o4x = w4s * cx, o4y = w4s * cy, o4z = w4s * cz;

    // Stage the 352-float row (stride-3: gcd(3,32)=1 -> conflict-free)
    float* r = sm_o[wb];
    r[lane]                = o0;
    r[MULC + 3 * lane + 0] = o1x;
    r[MULC + 3 * lane + 1] = o1y;
    r[MULC + 3 * lane + 2] = o1z;
    r[128  + 3 * lane + 0] = o2x;
    r[128  + 3 * lane + 1] = o2y;
    r[128  + 3 * lane + 2] = o2z;
    r[224  + lane]         = o3;
    r[256  + 3 * lane + 0] = o4x;
    r[256  + 3 * lane + 1] = o4y;
    r[256  + 3 * lane + 2] = o4z;
    __syncwarp();

    // TMA bulk-reduce: engine reads smem row, f32-adds into out[dst].
    if (lane == 0) {
        // Make the generic-proxy smem writes visible to the async proxy.
        asm volatile("fence.proxy.async.shared::cta;" ::: "memory");
        float*   gptr  = out + (long long)d * ROWF;
        uint32_t saddr = smem_u32(r);
        asm volatile(
            "cp.reduce.async.bulk.global.shared::cta.bulk_group.add.f32 "
            "[%0], [%1], %2;"
            :: "l"(gptr), "r"(saddr), "r"((int)(ROWF * sizeof(float)))
            : "memory");
        asm volatile("cp.async.bulk.commit_group;" ::: "memory");
        // Row is written once per warp; only completion before exit is needed.
        asm volatile("cp.async.bulk.wait_group 0;" ::: "memory");
    }
}

extern "C" void kernel_launch(void* const* d_in, const int* in_sizes, int n_in,
                              void* d_out, int out_size) {
    const float* x           = (const float*)d_in[0];
    const float* edge_attr   = (const float*)d_in[1];
    const float* edge_weight = (const float*)d_in[2];
    const int*   edge_dst    = (const int*)d_in[3];
    const int*   edge_src    = (const int*)d_in[4];
    float* out = (float*)d_out;

    const int E = in_sizes[3];

    int n4 = out_size / 4;
    tps_zero_kernel<<<(n4 + 255) / 256, 256>>>((float4*)out, n4);

    int blocks = (E + WARPS_PER_BLOCK - 1) / WARPS_PER_BLOCK;
    tps_scatter_kernel<<<blocks, WARPS_PER_BLOCK * 32>>>(
        x, edge_attr, edge_weight, edge_dst, edge_src, out, E);
}